// round 1
// baseline (speedup 1.0000x reference)
#include <cuda_runtime.h>

static constexpr int NNODES = 10000;
static constexpr int NE     = 640000;
static constexpr int DIN    = 128;
static constexpr int DHID   = 256;
static constexpr int DOUT   = 64;

// Scratch (allocation-free rule: __device__ globals)
__device__ float g_s1[NNODES * DIN];    // layer-1 scatter accumulator
__device__ float g_x [NNODES * DHID];   // layer-1 output (post relu)
__device__ float g_s2[NNODES * DHID];   // layer-2 scatter accumulator
__device__ float g_deg[NNODES];         // degree -> inverse degree (in place)

// ---------------------------------------------------------------------------
// Zero the accumulators + deg
// ---------------------------------------------------------------------------
__global__ void zero3_kernel() {
    int i = blockIdx.x * blockDim.x + threadIdx.x;
    int stride = gridDim.x * blockDim.x;
    float4 z = make_float4(0.f, 0.f, 0.f, 0.f);
    float4* s1 = reinterpret_cast<float4*>(g_s1);
    float4* s2 = reinterpret_cast<float4*>(g_s2);
    float4* dg = reinterpret_cast<float4*>(g_deg);
    for (int j = i; j < NNODES * DIN  / 4; j += stride) s1[j] = z;
    for (int j = i; j < NNODES * DHID / 4; j += stride) s2[j] = z;
    for (int j = i; j < NNODES / 4;        j += stride) dg[j] = z;
}

// ---------------------------------------------------------------------------
// Edge scatter: one warp per edge. lane covers D/32 floats via float4.
// s[dst] += h[src] * w  using vectorized red.global.add.v4.f32 (sm_90+).
// ---------------------------------------------------------------------------
template<int D, bool COUNT_DEG>
__global__ __launch_bounds__(256)
void scatter_kernel(const float* __restrict__ h, const float* __restrict__ w,
                    const int* __restrict__ src, const int* __restrict__ dst,
                    float* __restrict__ s, float* __restrict__ deg) {
    int gw   = (blockIdx.x * blockDim.x + threadIdx.x) >> 5;
    int lane = threadIdx.x & 31;
    if (gw >= NE) return;

    int   se = __ldg(src + gw);
    int   de = __ldg(dst + gw);
    float we = __ldg(w + gw);

    if (COUNT_DEG && lane == 0) atomicAdd(deg + de, 1.0f);

    const float4* hp = reinterpret_cast<const float4*>(h + (size_t)se * D);
    float*        sp = s + (size_t)de * D;

#pragma unroll
    for (int i = 0; i < D / 128; ++i) {
        float4 v = hp[lane + 32 * i];
        v.x *= we; v.y *= we; v.z *= we; v.w *= we;
        float* p = sp + (lane + 32 * i) * 4;
        asm volatile("red.global.add.v4.f32 [%0], {%1, %2, %3, %4};"
                     :: "l"(p), "f"(v.x), "f"(v.y), "f"(v.z), "f"(v.w)
                     : "memory");
    }
}

// ---------------------------------------------------------------------------
// deg -> invdeg in place:  invdeg = deg > 0 ? 1/deg : 0
// (matches ref: where(deg>0, s/max(deg,1), 0) since deg is an integer count)
// ---------------------------------------------------------------------------
__global__ void invdeg_kernel() {
    int i = blockIdx.x * blockDim.x + threadIdx.x;
    if (i < NNODES) {
        float d = g_deg[i];
        g_deg[i] = (d > 0.f) ? (1.0f / d) : 0.0f;
    }
}

// ---------------------------------------------------------------------------
// C[M, NN_] = act( concat(A1, A2 * invdeg[row]) @ W + bias )
// A1, A2: [M, K1] row-major; W: [2*K1, NN_] row-major.
// Block tile 64x64, BK=16, 256 threads, 4x4 microtile per thread.
// ---------------------------------------------------------------------------
template<int K1, int NN_, bool RELU>
__global__ __launch_bounds__(256)
void gemm_concat_kernel(const float* __restrict__ A1, const float* __restrict__ A2,
                        const float* __restrict__ invdeg,
                        const float* __restrict__ W, const float* __restrict__ bias,
                        float* __restrict__ C) {
    constexpr int BM = 64, BN = 64, BK = 16;
    constexpr int K  = 2 * K1;
    const int M = NNODES;

    __shared__ float As[BK][BM];   // transposed: As[k][m]
    __shared__ float Bs[BK][BN];

    int tid  = threadIdx.x;
    int row0 = blockIdx.x * BM;
    int col0 = blockIdx.y * BN;

    // A-tile load mapping: each thread loads one float4 along K
    int a_row = tid >> 2;          // 0..63
    int a_k4  = (tid & 3) * 4;     // 0,4,8,12
    int a_m   = row0 + a_row;
    bool a_ok = (a_m < M);
    float a_inv = a_ok ? invdeg[a_m] : 0.f;

    // B-tile load mapping
    int b_row = tid >> 4;          // 0..15
    int b_c4  = (tid & 15) * 4;    // 0..60

    int ty = tid >> 4;             // 0..15
    int tx = tid & 15;             // 0..15
    int cm = ty * 4;
    int cn = tx * 4;

    float acc[4][4] = {};

    for (int kb = 0; kb < K; kb += BK) {
        float4 av = make_float4(0.f, 0.f, 0.f, 0.f);
        if (a_ok) {
            int kg = kb + a_k4;
            if (kg < K1) {
                av = *reinterpret_cast<const float4*>(A1 + (size_t)a_m * K1 + kg);
            } else {
                av = *reinterpret_cast<const float4*>(A2 + (size_t)a_m * K1 + (kg - K1));
                av.x *= a_inv; av.y *= a_inv; av.z *= a_inv; av.w *= a_inv;
            }
        }
        As[a_k4 + 0][a_row] = av.x;
        As[a_k4 + 1][a_row] = av.y;
        As[a_k4 + 2][a_row] = av.z;
        As[a_k4 + 3][a_row] = av.w;

        *reinterpret_cast<float4*>(&Bs[b_row][b_c4]) =
            *reinterpret_cast<const float4*>(W + (size_t)(kb + b_row) * NN_ + col0 + b_c4);

        __syncthreads();

#pragma unroll
        for (int kk = 0; kk < BK; ++kk) {
            float4 a = *reinterpret_cast<const float4*>(&As[kk][cm]);
            float4 b = *reinterpret_cast<const float4*>(&Bs[kk][cn]);
            float ar[4] = {a.x, a.y, a.z, a.w};
            float br[4] = {b.x, b.y, b.z, b.w};
#pragma unroll
            for (int i = 0; i < 4; ++i)
#pragma unroll
                for (int j = 0; j < 4; ++j)
                    acc[i][j] = fmaf(ar[i], br[j], acc[i][j]);
        }
        __syncthreads();
    }

    float4 bv = *reinterpret_cast<const float4*>(bias + col0 + cn);
    float bb[4] = {bv.x, bv.y, bv.z, bv.w};
#pragma unroll
    for (int i = 0; i < 4; ++i) {
        int m = row0 + cm + i;
        if (m < M) {
            float4 o;
            float v0 = acc[i][0] + bb[0];
            float v1 = acc[i][1] + bb[1];
            float v2 = acc[i][2] + bb[2];
            float v3 = acc[i][3] + bb[3];
            if (RELU) {
                v0 = fmaxf(v0, 0.f); v1 = fmaxf(v1, 0.f);
                v2 = fmaxf(v2, 0.f); v3 = fmaxf(v3, 0.f);
            }
            o.x = v0; o.y = v1; o.z = v2; o.w = v3;
            *reinterpret_cast<float4*>(C + (size_t)m * NN_ + col0 + cn) = o;
        }
    }
}

// ---------------------------------------------------------------------------
extern "C" void kernel_launch(void* const* d_in, const int* in_sizes, int n_in,
                              void* d_out, int out_size) {
    const float* h   = (const float*)d_in[0];
    const float* w   = (const float*)d_in[1];
    const int*   src = (const int*)  d_in[2];
    const int*   dst = (const int*)  d_in[3];
    const float* W1  = (const float*)d_in[4];
    const float* b1  = (const float*)d_in[5];
    const float* W2  = (const float*)d_in[6];
    const float* b2  = (const float*)d_in[7];
    float* out = (float*)d_out;

    float *s1, *x, *s2, *deg;
    cudaGetSymbolAddress((void**)&s1,  g_s1);
    cudaGetSymbolAddress((void**)&x,   g_x);
    cudaGetSymbolAddress((void**)&s2,  g_s2);
    cudaGetSymbolAddress((void**)&deg, g_deg);

    // 1. zero accumulators + deg
    zero3_kernel<<<2500, 256>>>();

    // 2. layer-1 edge scatter (+ degree count): s1[dst] += h[src]*w
    int scatter_blocks = (NE * 32 + 255) / 256;   // one warp per edge
    scatter_kernel<DIN, true><<<scatter_blocks, 256>>>(h, w, src, dst, s1, deg);

    // 3. deg -> invdeg
    invdeg_kernel<<<(NNODES + 255) / 256, 256>>>();

    // 4. x = relu(concat(h, s1*invdeg) @ W1 + b1)
    dim3 g1((NNODES + 63) / 64, DHID / 64);
    gemm_concat_kernel<DIN, DHID, true><<<g1, 256>>>(h, s1, deg, W1, b1, x);

    // 5. layer-2 edge scatter: s2[dst] += x[src]*w
    scatter_kernel<DHID, false><<<scatter_blocks, 256>>>(x, w, src, dst, s2, deg);

    // 6. out = concat(x, s2*invdeg) @ W2 + b2
    dim3 g2((NNODES + 63) / 64, DOUT / 64);
    gemm_concat_kernel<DHID, DOUT, false><<<g2, 256>>>(x, s2, deg, W2, b2, out);
}

// round 2
// speedup vs baseline: 2.4875x; 2.4875x over previous
#include <cuda_runtime.h>

static constexpr int NNODES = 10000;
static constexpr int NE     = 640000;
static constexpr int DIN    = 128;
static constexpr int DHID   = 256;
static constexpr int DOUT   = 64;

// ---- scratch (__device__ globals: allocation-free rule) ----
__device__ int   g_cnt[NNODES];
__device__ int   g_off[NNODES + 1];
__device__ int   g_cur[NNODES];
__device__ int2  g_edges[NE];            // (src, w bits) sorted by dst
__device__ float g_hN[NNODES * DIN];     // layer-1 mean aggregate (normalized)
__device__ float g_x [NNODES * DHID];    // layer-1 output (post relu)
__device__ float g_y [NNODES * DOUT];    // x @ W2_bot

// ---------------------------------------------------------------------------
// CSR build: zero counts -> count -> scan -> fill
// ---------------------------------------------------------------------------
__global__ void zero_cnt_kernel() {
    int i = blockIdx.x * blockDim.x + threadIdx.x;
    if (i < NNODES) g_cnt[i] = 0;
}

__global__ void count_kernel(const int* __restrict__ dst) {
    int e = blockIdx.x * blockDim.x + threadIdx.x;
    if (e < NE) atomicAdd(&g_cnt[dst[e]], 1);
}

__global__ void scan_kernel() {
    __shared__ int sh[1024];
    constexpr int CH = 10;                // 1024*10 >= 10000
    int t = threadIdx.x;
    int base = t * CH;
    int loc[CH];
    int sum = 0;
#pragma unroll
    for (int i = 0; i < CH; ++i) {
        int idx = base + i;
        int v = (idx < NNODES) ? g_cnt[idx] : 0;
        loc[i] = sum;
        sum += v;
    }
    sh[t] = sum;
    __syncthreads();
    for (int d = 1; d < 1024; d <<= 1) {
        int v = (t >= d) ? sh[t - d] : 0;
        __syncthreads();
        sh[t] += v;
        __syncthreads();
    }
    int excl = (t > 0) ? sh[t - 1] : 0;
#pragma unroll
    for (int i = 0; i < CH; ++i) {
        int idx = base + i;
        if (idx < NNODES) {
            g_off[idx] = excl + loc[i];
            g_cur[idx] = excl + loc[i];
        }
    }
    if (t == 1023) g_off[NNODES] = sh[1023];
}

__global__ void fill_kernel(const int* __restrict__ src, const int* __restrict__ dst,
                            const float* __restrict__ w) {
    int e = blockIdx.x * blockDim.x + threadIdx.x;
    if (e < NE) {
        int d = dst[e];
        int p = atomicAdd(&g_cur[d], 1);
        g_edges[p] = make_int2(src[e], __float_as_int(w[e]));
    }
}

// ---------------------------------------------------------------------------
// gather1: hN[n] = (1/deg) * sum_{e: dst=n} h[src_e] * w_e      (D = 128)
// one warp per node, lane holds float4
// ---------------------------------------------------------------------------
__global__ __launch_bounds__(256)
void gather1_kernel(const float* __restrict__ h) {
    int gw = (blockIdx.x * blockDim.x + threadIdx.x) >> 5;
    if (gw >= NNODES) return;
    int lane = threadIdx.x & 31;
    int s = g_off[gw], e = g_off[gw + 1];
    float4 acc = make_float4(0.f, 0.f, 0.f, 0.f);
    int j = s;
    // unroll by 2 for MLP
    for (; j + 1 < e; j += 2) {
        int2 e0 = g_edges[j];
        int2 e1 = g_edges[j + 1];
        float w0 = __int_as_float(e0.y);
        float w1 = __int_as_float(e1.y);
        float4 v0 = *reinterpret_cast<const float4*>(h + (size_t)e0.x * DIN + lane * 4);
        float4 v1 = *reinterpret_cast<const float4*>(h + (size_t)e1.x * DIN + lane * 4);
        acc.x = fmaf(v0.x, w0, acc.x); acc.y = fmaf(v0.y, w0, acc.y);
        acc.z = fmaf(v0.z, w0, acc.z); acc.w = fmaf(v0.w, w0, acc.w);
        acc.x = fmaf(v1.x, w1, acc.x); acc.y = fmaf(v1.y, w1, acc.y);
        acc.z = fmaf(v1.z, w1, acc.z); acc.w = fmaf(v1.w, w1, acc.w);
    }
    if (j < e) {
        int2 e0 = g_edges[j];
        float w0 = __int_as_float(e0.y);
        float4 v0 = *reinterpret_cast<const float4*>(h + (size_t)e0.x * DIN + lane * 4);
        acc.x = fmaf(v0.x, w0, acc.x); acc.y = fmaf(v0.y, w0, acc.y);
        acc.z = fmaf(v0.z, w0, acc.z); acc.w = fmaf(v0.w, w0, acc.w);
    }
    float inv = (e > s) ? 1.0f / (float)(e - s) : 0.0f;
    acc.x *= inv; acc.y *= inv; acc.z *= inv; acc.w *= inv;
    *reinterpret_cast<float4*>(g_hN + (size_t)gw * DIN + lane * 4) = acc;
}

// ---------------------------------------------------------------------------
// gather2: out[n] += (1/deg) * sum_{e: dst=n} y[src_e] * w_e     (D = 64)
// one warp per node, lane holds float2
// ---------------------------------------------------------------------------
__global__ __launch_bounds__(256)
void gather2_kernel(float* __restrict__ out) {
    int gw = (blockIdx.x * blockDim.x + threadIdx.x) >> 5;
    if (gw >= NNODES) return;
    int lane = threadIdx.x & 31;
    int s = g_off[gw], e = g_off[gw + 1];
    float2 acc = make_float2(0.f, 0.f);
    int j = s;
    for (; j + 1 < e; j += 2) {
        int2 e0 = g_edges[j];
        int2 e1 = g_edges[j + 1];
        float w0 = __int_as_float(e0.y);
        float w1 = __int_as_float(e1.y);
        float2 v0 = *reinterpret_cast<const float2*>(g_y + (size_t)e0.x * DOUT + lane * 2);
        float2 v1 = *reinterpret_cast<const float2*>(g_y + (size_t)e1.x * DOUT + lane * 2);
        acc.x = fmaf(v0.x, w0, acc.x); acc.y = fmaf(v0.y, w0, acc.y);
        acc.x = fmaf(v1.x, w1, acc.x); acc.y = fmaf(v1.y, w1, acc.y);
    }
    if (j < e) {
        int2 e0 = g_edges[j];
        float w0 = __int_as_float(e0.y);
        float2 v0 = *reinterpret_cast<const float2*>(g_y + (size_t)e0.x * DOUT + lane * 2);
        acc.x = fmaf(v0.x, w0, acc.x); acc.y = fmaf(v0.y, w0, acc.y);
    }
    float inv = (e > s) ? 1.0f / (float)(e - s) : 0.0f;
    float2* op = reinterpret_cast<float2*>(out + (size_t)gw * DOUT + lane * 2);
    float2 cur = *op;
    cur.x = fmaf(acc.x, inv, cur.x);
    cur.y = fmaf(acc.y, inv, cur.y);
    *op = cur;
}

// ---------------------------------------------------------------------------
// gemm1: x = relu( [h | hN] @ W1 + b1 )   M=10000, K=256, N=256
// BM=BN=64, BK=16, 64 threads, 8x8 microtile
// ---------------------------------------------------------------------------
__global__ __launch_bounds__(64)
void gemm1_kernel(const float* __restrict__ A1, const float* __restrict__ A2,
                  const float* __restrict__ W, const float* __restrict__ bias,
                  float* __restrict__ C) {
    constexpr int BM = 64, BN = 64, BK = 16, K = 256, K1 = 128, NT = 256;
    __shared__ float As[BK][BM];
    __shared__ float Bs[BK][BN];

    int tid  = threadIdx.x;
    int row0 = blockIdx.x * BM;
    int col0 = blockIdx.y * BN;

    int a_m  = row0 + tid;
    bool a_ok = (a_m < NNODES);

    int b_r0 = tid >> 4;           // 0..3
    int b_c4 = (tid & 15) * 4;     // 0..60

    int ty = tid >> 3, tx = tid & 7;
    int cm = ty * 8, cn = tx * 8;

    float acc[8][8] = {};

    for (int kb = 0; kb < K; kb += BK) {
        const float* Ab = (kb < K1) ? A1 : A2;
        int kloc = (kb < K1) ? kb : kb - K1;
        const float* arow = Ab + (size_t)a_m * K1 + kloc;
#pragma unroll
        for (int q = 0; q < 4; ++q) {
            float4 av = make_float4(0.f, 0.f, 0.f, 0.f);
            if (a_ok) av = *reinterpret_cast<const float4*>(arow + q * 4);
            As[q * 4 + 0][tid] = av.x;
            As[q * 4 + 1][tid] = av.y;
            As[q * 4 + 2][tid] = av.z;
            As[q * 4 + 3][tid] = av.w;
        }
#pragma unroll
        for (int q = 0; q < 4; ++q) {
            int kr = b_r0 + q * 4;  // 0..15
            *reinterpret_cast<float4*>(&Bs[kr][b_c4]) =
                *reinterpret_cast<const float4*>(W + (size_t)(kb + kr) * NT + col0 + b_c4);
        }
        __syncthreads();
#pragma unroll
        for (int kk = 0; kk < BK; ++kk) {
            float a[8], b[8];
            *reinterpret_cast<float4*>(a)     = *reinterpret_cast<const float4*>(&As[kk][cm]);
            *reinterpret_cast<float4*>(a + 4) = *reinterpret_cast<const float4*>(&As[kk][cm + 4]);
            *reinterpret_cast<float4*>(b)     = *reinterpret_cast<const float4*>(&Bs[kk][cn]);
            *reinterpret_cast<float4*>(b + 4) = *reinterpret_cast<const float4*>(&Bs[kk][cn + 4]);
#pragma unroll
            for (int i = 0; i < 8; ++i)
#pragma unroll
                for (int jj = 0; jj < 8; ++jj)
                    acc[i][jj] = fmaf(a[i], b[jj], acc[i][jj]);
        }
        __syncthreads();
    }

#pragma unroll
    for (int i = 0; i < 8; ++i) {
        int m = row0 + cm + i;
        if (m < NNODES) {
#pragma unroll
            for (int j0 = 0; j0 < 8; j0 += 4) {
                float4 o;
                o.x = fmaxf(acc[i][j0 + 0] + bias[col0 + cn + j0 + 0], 0.f);
                o.y = fmaxf(acc[i][j0 + 1] + bias[col0 + cn + j0 + 1], 0.f);
                o.z = fmaxf(acc[i][j0 + 2] + bias[col0 + cn + j0 + 2], 0.f);
                o.w = fmaxf(acc[i][j0 + 3] + bias[col0 + cn + j0 + 3], 0.f);
                *reinterpret_cast<float4*>(C + (size_t)m * NT + col0 + cn + j0) = o;
            }
        }
    }
}

// ---------------------------------------------------------------------------
// gemm2: blockIdx.y==0: out = x @ W2[0:256]   + b2   (written to d_out)
//        blockIdx.y==1: y   = x @ W2[256:512]        (written to g_y)
// M=10000, K=256, N=64 each.  BM=BN=64, BK=16, 64 threads, 8x8 microtile
// ---------------------------------------------------------------------------
__global__ __launch_bounds__(64)
void gemm2_kernel(const float* __restrict__ A, const float* __restrict__ W2,
                  const float* __restrict__ bias, float* __restrict__ out,
                  float* __restrict__ Y) {
    constexpr int BM = 64, BN = 64, BK = 16, K = 256, KA = 256;
    __shared__ float As[BK][BM];
    __shared__ float Bs[BK][BN];

    int tid  = threadIdx.x;
    int row0 = blockIdx.x * BM;
    bool top = (blockIdx.y == 0);
    const float* W = top ? W2 : (W2 + (size_t)256 * DOUT);

    int a_m  = row0 + tid;
    bool a_ok = (a_m < NNODES);

    int b_r0 = tid >> 4;
    int b_c4 = (tid & 15) * 4;

    int ty = tid >> 3, tx = tid & 7;
    int cm = ty * 8, cn = tx * 8;

    float acc[8][8] = {};

    for (int kb = 0; kb < K; kb += BK) {
        const float* arow = A + (size_t)a_m * KA + kb;
#pragma unroll
        for (int q = 0; q < 4; ++q) {
            float4 av = make_float4(0.f, 0.f, 0.f, 0.f);
            if (a_ok) av = *reinterpret_cast<const float4*>(arow + q * 4);
            As[q * 4 + 0][tid] = av.x;
            As[q * 4 + 1][tid] = av.y;
            As[q * 4 + 2][tid] = av.z;
            As[q * 4 + 3][tid] = av.w;
        }
#pragma unroll
        for (int q = 0; q < 4; ++q) {
            int kr = b_r0 + q * 4;
            *reinterpret_cast<float4*>(&Bs[kr][b_c4]) =
                *reinterpret_cast<const float4*>(W + (size_t)(kb + kr) * DOUT + b_c4);
        }
        __syncthreads();
#pragma unroll
        for (int kk = 0; kk < BK; ++kk) {
            float a[8], b[8];
            *reinterpret_cast<float4*>(a)     = *reinterpret_cast<const float4*>(&As[kk][cm]);
            *reinterpret_cast<float4*>(a + 4) = *reinterpret_cast<const float4*>(&As[kk][cm + 4]);
            *reinterpret_cast<float4*>(b)     = *reinterpret_cast<const float4*>(&Bs[kk][cn]);
            *reinterpret_cast<float4*>(b + 4) = *reinterpret_cast<const float4*>(&Bs[kk][cn + 4]);
#pragma unroll
            for (int i = 0; i < 8; ++i)
#pragma unroll
                for (int jj = 0; jj < 8; ++jj)
                    acc[i][jj] = fmaf(a[i], b[jj], acc[i][jj]);
        }
        __syncthreads();
    }

#pragma unroll
    for (int i = 0; i < 8; ++i) {
        int m = row0 + cm + i;
        if (m < NNODES) {
#pragma unroll
            for (int j0 = 0; j0 < 8; j0 += 4) {
                float4 o;
                if (top) {
                    o.x = acc[i][j0 + 0] + bias[cn + j0 + 0];
                    o.y = acc[i][j0 + 1] + bias[cn + j0 + 1];
                    o.z = acc[i][j0 + 2] + bias[cn + j0 + 2];
                    o.w = acc[i][j0 + 3] + bias[cn + j0 + 3];
                    *reinterpret_cast<float4*>(out + (size_t)m * DOUT + cn + j0) = o;
                } else {
                    o.x = acc[i][j0 + 0];
                    o.y = acc[i][j0 + 1];
                    o.z = acc[i][j0 + 2];
                    o.w = acc[i][j0 + 3];
                    *reinterpret_cast<float4*>(Y + (size_t)m * DOUT + cn + j0) = o;
                }
            }
        }
    }
}

// ---------------------------------------------------------------------------
extern "C" void kernel_launch(void* const* d_in, const int* in_sizes, int n_in,
                              void* d_out, int out_size) {
    const float* h   = (const float*)d_in[0];
    const float* w   = (const float*)d_in[1];
    const int*   src = (const int*)  d_in[2];
    const int*   dst = (const int*)  d_in[3];
    const float* W1  = (const float*)d_in[4];
    const float* b1  = (const float*)d_in[5];
    const float* W2  = (const float*)d_in[6];
    const float* b2  = (const float*)d_in[7];
    float* out = (float*)d_out;

    float *hN, *x, *y;
    cudaGetSymbolAddress((void**)&hN, g_hN);
    cudaGetSymbolAddress((void**)&x,  g_x);
    cudaGetSymbolAddress((void**)&y,  g_y);

    // CSR build (by dst)
    zero_cnt_kernel<<<(NNODES + 255) / 256, 256>>>();
    count_kernel<<<(NE + 255) / 256, 256>>>(dst);
    scan_kernel<<<1, 1024>>>();
    fill_kernel<<<(NE + 255) / 256, 256>>>(src, dst, w);

    // layer 1: gather (mean, normalized) then GEMM+relu
    gather1_kernel<<<(NNODES * 32 + 255) / 256, 256>>>(h);
    dim3 g1((NNODES + 63) / 64, DHID / 64);
    gemm1_kernel<<<g1, 64>>>(h, hN, W1, b1, x);

    // layer 2 via linearity: out = x@W2_top + b2 ; y = x@W2_bot ; out += agg(y)
    dim3 g2((NNODES + 63) / 64, 2);
    gemm2_kernel<<<g2, 64>>>(x, W2, b2, out, y);
    gather2_kernel<<<(NNODES * 32 + 255) / 256, 256>>>(out);
}